// round 15
// baseline (speedup 1.0000x reference)
#include <cuda_runtime.h>
#include <cuda_fp16.h>
#include <cstdint>

#define H 256
#define NGRAPH 128
#define MAXN   20224
#define MAXEG  200192
#define MAXELG 400128

// ---------------- scratch ----------------
__device__ float g_AB[(size_t)MAXN * 512];
__device__ float g_h[(size_t)MAXEG * H];
__device__ float g_nbg[(size_t)MAXEG * 4];
__device__ float g_ebg[(size_t)MAXELG * 4];
__device__ float g_bnacc[2 * H];
__device__ float g_bnscale[H];
__device__ float g_bnshift[H];
__device__ float g_gsum[NGRAPH * H];
__device__ float g_cnt[NGRAPH];

// CSR scratch
__device__ int g_deg[MAXEG];
__device__ int g_cursor[MAXEG];
__device__ int g_blk[1024];
__device__ int g_rowptr_lg[MAXEG + 1];
__device__ int g_eidx_lg[MAXELG];
__device__ int g_rowptr_g[MAXN + 1];
__device__ int g_eidx_g[MAXEG];

// fp16 activation buffers
__device__ __half g_node[(size_t)MAXN * H];
__device__ __half g_act[(size_t)MAXEG * H];
__device__ __half g_hid[(size_t)MAXEG * 2 * H];

// transposed/split fp16 weights arena
#define OFF_WMSG 0
#define OFF_W1T  (512 * 256)
#define OFF_W2T  (OFF_W1T + 4 * 131072)
#define WT_TOTAL (OFF_W2T + 4 * 131072)
__device__ __half g_wthi[WT_TOTAL];
__device__ __half g_wtlo[WT_TOTAL];

// ======================= helpers =======================
__device__ __forceinline__ uint32_t smem_u32(const void* p) {
    uint32_t a;
    asm("{ .reg .u64 t; cvta.to.shared.u64 t, %1; cvt.u32.u64 %0, t; }" : "=r"(a) : "l"(p));
    return a;
}
#define CP16(dst, src) \
    asm volatile("cp.async.cg.shared.global [%0], [%1], 16;" :: "r"(dst), "l"(src) : "memory")
#define CP16_CA(dst, src) \
    asm volatile("cp.async.ca.shared.global [%0], [%1], 16;" :: "r"(dst), "l"(src) : "memory")
#define CP_COMMIT() asm volatile("cp.async.commit_group;" ::: "memory")
#define CP_WAIT1()  asm volatile("cp.async.wait_group 1;" ::: "memory")
#define CP_WAIT0()  asm volatile("cp.async.wait_group 0;" ::: "memory")

__device__ __forceinline__ void ldm4(uint32_t (&r)[4], uint32_t addr) {
    asm volatile("ldmatrix.sync.aligned.m8n8.x4.shared.b16 {%0,%1,%2,%3}, [%4];"
                 : "=r"(r[0]), "=r"(r[1]), "=r"(r[2]), "=r"(r[3]) : "r"(addr));
}
__device__ __forceinline__ void mma_f16(float (&d)[4], const uint32_t (&a)[4], const uint32_t* b) {
    asm volatile(
        "mma.sync.aligned.m16n8k16.row.col.f32.f16.f16.f32 "
        "{%0,%1,%2,%3}, {%4,%5,%6,%7}, {%8,%9}, {%0,%1,%2,%3};"
        : "+f"(d[0]), "+f"(d[1]), "+f"(d[2]), "+f"(d[3])
        : "r"(a[0]), "r"(a[1]), "r"(a[2]), "r"(a[3]), "r"(b[0]), "r"(b[1]));
}

// ======================= CSR build kernels =======================
__global__ void zero_int_kernel(int* a, int n)
{
    int i = blockIdx.x * 256 + threadIdx.x;
    if (i < n) a[i] = 0;
}
__global__ void hist_kernel(const int* __restrict__ dst, int* __restrict__ deg, int E)
{
    int i = blockIdx.x * 256 + threadIdx.x;
    if (i < E) atomicAdd(&deg[dst[i]], 1);
}
__global__ void scan_block_sums(const int* __restrict__ deg, int* __restrict__ blk, int n)
{
    __shared__ int sd[256];
    int t = threadIdx.x;
    int i = blockIdx.x * 256 + t;
    sd[t] = (i < n) ? deg[i] : 0;
    __syncthreads();
    for (int o = 128; o > 0; o >>= 1) {
        if (t < o) sd[t] += sd[t + o];
        __syncthreads();
    }
    if (t == 0) blk[blockIdx.x] = sd[0];
}
__global__ void scan_single_block(int* blk, int nb)
{
    __shared__ int tmp[1024];
    int t = threadIdx.x;
    int v = (t < nb) ? blk[t] : 0;
    tmp[t] = v;
    __syncthreads();
    for (int o = 1; o < 1024; o <<= 1) {
        int u = (t >= o) ? tmp[t - o] : 0;
        __syncthreads();
        tmp[t] += u;
        __syncthreads();
    }
    if (t < nb) blk[t] = tmp[t] - v;
}
__global__ void scan_final(const int* __restrict__ deg, const int* __restrict__ blk,
                           int* __restrict__ rowptr, int* __restrict__ cursor, int n, int E)
{
    __shared__ int tmp[256];
    int t = threadIdx.x;
    int i = blockIdx.x * 256 + t;
    int v = (i < n) ? deg[i] : 0;
    tmp[t] = v;
    __syncthreads();
    for (int o = 1; o < 256; o <<= 1) {
        int u = (t >= o) ? tmp[t - o] : 0;
        __syncthreads();
        tmp[t] += u;
        __syncthreads();
    }
    int excl = tmp[t] - v + blk[blockIdx.x];
    if (i < n) { rowptr[i] = excl; cursor[i] = excl; }
    if (blockIdx.x == 0 && t == 0) rowptr[n] = E;
}
__global__ void fill_csr_kernel(const int* __restrict__ dst, int* __restrict__ cursor,
                                int* __restrict__ eidx, int E)
{
    int e = blockIdx.x * 256 + threadIdx.x;
    if (e < E) {
        int p = atomicAdd(&cursor[dst[e]], 1);
        eidx[p] = e;
    }
}

// ======================= mma.sync 2-term fp16 GEMM =======================
// CTA 128x64, 8 warps of 32x32, BK=32, 3 stages, 3 CTAs/SM (24 warps).
// flags: 1=bias, 2=relu, 4=residual fp32, 8=fp16 out, 32=BN stats
#define RB 80
#define A_TILE_B (128 * RB)       // 10240
#define B_TILE_B (64 * RB)        // 5120
#define SO_A   0
#define SO_BHI A_TILE_B
#define SO_BLO (A_TILE_B + B_TILE_B)
#define STAGE_B (A_TILE_B + 2 * B_TILE_B)   // 20480
#define GEMM_SMEM (3 * STAGE_B)             // 61440

__device__ __forceinline__ void load_stage(uint32_t sbase,
    const __half* __restrict__ A, const __half* __restrict__ B_hi,
    const __half* __restrict__ B_lo,
    int K, int m0, int n0, int k0, int tid)
{
#pragma unroll
    for (int i = 0; i < 2; i++) {            // A: 128 rows x 4 chunks
        int g = tid + i * 256;
        int row = g >> 2, ch = g & 3;
        uint32_t so = (uint32_t)row * RB + (uint32_t)ch * 16;
        size_t ao = (size_t)(m0 + row) * K + k0 + ch * 8;
        CP16_CA(sbase + SO_A + so, A + ao);
    }
    {                                         // B: 64 rows x 4 chunks, hi+lo
        int row = tid >> 2, ch = tid & 3;
        uint32_t so = (uint32_t)row * RB + (uint32_t)ch * 16;
        size_t bo = (size_t)(n0 + row) * K + k0 + ch * 8;
        CP16(sbase + SO_BHI + so, B_hi + bo);
        CP16(sbase + SO_BLO + so, B_lo + bo);
    }
}

__global__ __launch_bounds__(256, 3) void mma_gemm_kernel(
    const __half* __restrict__ A,
    const __half* __restrict__ Bhi, const __half* __restrict__ Blo,
    const float* __restrict__ bias, const float* __restrict__ res,
    float* __restrict__ Cf, __half* __restrict__ Ch, float* __restrict__ bnacc,
    int M, int N, int K, int flags)
{
    extern __shared__ __align__(128) char smem[];
    uint32_t sb = smem_u32(smem);
    int tid = threadIdx.x;
    int wid = tid >> 5, lane = tid & 31;
    int m0 = blockIdx.y * 128, n0 = blockIdx.x * 64;
    int nk = K >> 5;

    load_stage(sb, A, Bhi, Blo, K, m0, n0, 0, tid);
    CP_COMMIT();
    load_stage(sb + STAGE_B, A, Bhi, Blo, K, m0, n0, 32, tid);
    CP_COMMIT();

    float acc[2][4][4];
#pragma unroll
    for (int i = 0; i < 2; i++)
#pragma unroll
        for (int j = 0; j < 4; j++)
#pragma unroll
            for (int q = 0; q < 4; q++) acc[i][j][q] = 0.f;

    int mo = (wid & 3) * 32, no = (wid >> 2) * 32;
    int a_row = mo + (lane & 15);
    int a_k8  = lane >> 4;
    int b_row = ((lane >> 4) << 3) + (lane & 7);
    int b_k8  = (lane >> 3) & 1;

    for (int k = 0; k < nk; k++) {
        if (k == nk - 1) { CP_WAIT0(); } else { CP_WAIT1(); }
        __syncthreads();
        uint32_t base = sb + (uint32_t)(k % 3) * STAGE_B;
        if (k + 2 < nk)
            load_stage(sb + (uint32_t)((k + 2) % 3) * STAGE_B, A, Bhi, Blo,
                       K, m0, n0, (k + 2) * 32, tid);
        CP_COMMIT();
#pragma unroll
        for (int k16 = 0; k16 < 2; k16++) {
            int kk8 = k16 * 2;
            uint32_t ah[2][4], bh[2][4], bl[2][4];
#pragma unroll
            for (int i = 0; i < 2; i++) {
                uint32_t aaddr = base + SO_A + (uint32_t)(a_row + i * 16) * RB
                               + (uint32_t)(kk8 + a_k8) * 16;
                ldm4(ah[i], aaddr);
            }
#pragma unroll
            for (int j = 0; j < 2; j++) {
                uint32_t baddr = base + SO_BHI + (uint32_t)(no + j * 16 + b_row) * RB
                               + (uint32_t)(kk8 + b_k8) * 16;
                ldm4(bh[j], baddr);
                ldm4(bl[j], baddr + (SO_BLO - SO_BHI));
            }
#pragma unroll
            for (int j = 0; j < 2; j++)
#pragma unroll
                for (int i = 0; i < 2; i++) {
                    mma_f16(acc[i][2 * j],     ah[i], &bh[j][0]);
                    mma_f16(acc[i][2 * j + 1], ah[i], &bh[j][2]);
                }
#pragma unroll
            for (int j = 0; j < 2; j++)
#pragma unroll
                for (int i = 0; i < 2; i++) {
                    mma_f16(acc[i][2 * j],     ah[i], &bl[j][0]);
                    mma_f16(acc[i][2 * j + 1], ah[i], &bl[j][2]);
                }
        }
    }

    // epilogue (+ optional fused BN statistics)
    float st[4][2], sq[4][2];
#pragma unroll
    for (int nb = 0; nb < 4; nb++) {
        st[nb][0] = st[nb][1] = 0.f;
        sq[nb][0] = sq[nb][1] = 0.f;
    }
#pragma unroll
    for (int i = 0; i < 2; i++) {
        int r0 = m0 + mo + i * 16 + (lane >> 2);
#pragma unroll
        for (int half = 0; half < 2; half++) {
            int r = r0 + half * 8;
            if (r >= M) continue;
#pragma unroll
            for (int nb = 0; nb < 4; nb++) {
                int col = n0 + no + nb * 8 + 2 * (lane & 3);
                float v0 = acc[i][nb][half * 2 + 0];
                float v1 = acc[i][nb][half * 2 + 1];
                if (flags & 1) { v0 += bias[col]; v1 += bias[col + 1]; }
                if (flags & 4) {
                    float2 t = *(const float2*)(res + (size_t)r * N + col);
                    v0 += t.x; v1 += t.y;
                }
                if (flags & 2) { v0 = fmaxf(v0, 0.f); v1 = fmaxf(v1, 0.f); }
                if (flags & 32) {
                    st[nb][0] += v0; sq[nb][0] = fmaf(v0, v0, sq[nb][0]);
                    st[nb][1] += v1; sq[nb][1] = fmaf(v1, v1, sq[nb][1]);
                }
                if (flags & 8) {
                    *(__half2*)(Ch + (size_t)r * N + col) =
                        __halves2half2(__float2half(v0), __float2half(v1));
                } else {
                    *(float2*)(Cf + (size_t)r * N + col) = make_float2(v0, v1);
                }
            }
        }
    }
    if (flags & 32) {
#pragma unroll
        for (int nb = 0; nb < 4; nb++)
#pragma unroll
            for (int w = 0; w < 2; w++) {
                float s = st[nb][w], q = sq[nb][w];
                s += __shfl_xor_sync(0xffffffffu, s, 4);
                q += __shfl_xor_sync(0xffffffffu, q, 4);
                s += __shfl_xor_sync(0xffffffffu, s, 8);
                q += __shfl_xor_sync(0xffffffffu, q, 8);
                s += __shfl_xor_sync(0xffffffffu, s, 16);
                q += __shfl_xor_sync(0xffffffffu, q, 16);
                if ((lane >> 2) == 0) {
                    int col = n0 + no + nb * 8 + 2 * (lane & 3) + w;
                    atomicAdd(&bnacc[col], s);
                    atomicAdd(&bnacc[N + col], q);
                }
            }
    }
}

// ---------------- ALL weight transpose+splits in one kernel --------------------
__global__ void tsplit_all_kernel(const float* __restrict__ Wmsg,
                                  const float* __restrict__ W1,
                                  const float* __restrict__ W2,
                                  __half* __restrict__ thi, __half* __restrict__ tlo)
{
    int idx = blockIdx.x * 256 + threadIdx.x;
    if (idx >= 1179648) return;
    float w;
    size_t dofs;
    if (idx < 131072) {
        int part = idx >> 16, e = idx & 65535;
        int k = e >> 8, n = e & 255;
        w = Wmsg[(size_t)part * 65536 + (size_t)k * 256 + n];
        dofs = (size_t)OFF_WMSG + part * 65536 + (size_t)n * 256 + k;
    } else if (idx < 655360) {
        int e = idx - 131072;
        int l = e >> 17, el = e & 131071;
        int k = el >> 9, n = el & 511;
        w = W1[(size_t)l * 131072 + (size_t)k * 512 + n];
        dofs = (size_t)OFF_W1T + (size_t)l * 131072 + (size_t)n * 256 + k;
    } else {
        int e = idx - 655360;
        int l = e >> 17, el = e & 131071;
        int k = el >> 8, n = el & 255;
        w = W2[(size_t)l * 131072 + (size_t)k * 256 + n];
        dofs = (size_t)OFF_W2T + (size_t)l * 131072 + (size_t)n * 512 + k;
    }
    __half hi = __float2half(w);
    __half lo = __float2half(w - __half2float(hi));
    thi[dofs] = hi;
    tlo[dofs] = lo;
}

// ---------------- node encoder (fp16 out) --------------------------------------
__global__ void enc_kernel(const float* __restrict__ xg, const float* __restrict__ W,
                           const float* __restrict__ b, __half* __restrict__ out)
{
    __shared__ float sx[16];
    int n = blockIdx.x, c = threadIdx.x;
    if (c < 16) sx[c] = xg[(size_t)n * 16 + c];
    __syncthreads();
    float v = b[c];
#pragma unroll
    for (int k = 0; k < 16; k++) v = fmaf(sx[k], W[k * H + c], v);
    out[(size_t)n * H + c] = __float2half(v);
}

// ---------------- combined tiny [.,4]@[4,4]+b projections ----------------------
__global__ void basis4_both_kernel(const float* __restrict__ in1, const float* __restrict__ W1,
                                   const float* __restrict__ b1v, float* __restrict__ out1, int E1,
                                   const float* __restrict__ in2, const float* __restrict__ W2,
                                   const float* __restrict__ b2v, float* __restrict__ out2, int E2)
{
    int e = blockIdx.x * blockDim.x + threadIdx.x;
    const float* in; const float* W; const float* b; float* out;
    if (e < E1) { in = in1; W = W1; b = b1v; out = out1; }
    else { e -= E1; if (e >= E2) return; in = in2; W = W2; b = b2v; out = out2; }
    float4 x = *(const float4*)(in + (size_t)e * 4);
    float o0 = b[0] + x.x * W[0] + x.y * W[4] + x.z * W[8]  + x.w * W[12];
    float o1 = b[1] + x.x * W[1] + x.y * W[5] + x.z * W[9]  + x.w * W[13];
    float o2 = b[2] + x.x * W[2] + x.y * W[6] + x.z * W[10] + x.w * W[14];
    float o3 = b[3] + x.x * W[3] + x.y * W[7] + x.z * W[11] + x.w * W[15];
    *(float4*)(out + (size_t)e * 4) = make_float4(o0, o1, o2, o3);
}

// ---------------- fused first-message ------------------------------------------
#define MEPB 16
__global__ __launch_bounds__(256) void msg_edge_kernel(
    const float* __restrict__ AB,
    const float* __restrict__ ea, const float* __restrict__ xlg,
    const float* __restrict__ Wc, const float* __restrict__ Wd,
    const float* __restrict__ bmsg,
    const int* __restrict__ srcg, const int* __restrict__ dstg,
    float* __restrict__ h, int Eg)
{
    __shared__ float sWc[16 * H];
    __shared__ float sWd[4 * H];
    __shared__ float sb[H];
    __shared__ float sea[MEPB][16];
    __shared__ float sxl[MEPB][4];
    int tid = threadIdx.x;
    for (int i = tid; i < 16 * H; i += 256) sWc[i] = Wc[i];
    for (int i = tid; i < 4 * H; i += 256) sWd[i] = Wd[i];
    sb[tid] = bmsg[tid];
    int e0 = blockIdx.x * MEPB;
    for (int i = tid; i < MEPB * 16; i += 256) {
        int e = e0 + i / 16;
        if (e < Eg) sea[i / 16][i % 16] = ea[(size_t)e * 16 + (i % 16)];
    }
    for (int i = tid; i < MEPB * 4; i += 256) {
        int e = e0 + i / 4;
        if (e < Eg) sxl[i / 4][i % 4] = xlg[(size_t)e * 4 + (i % 4)];
    }
    __syncthreads();
    int c = tid;
    for (int i = 0; i < MEPB; i++) {
        int e = e0 + i;
        if (e >= Eg) break;
        int s = srcg[e], d = dstg[e];
        float v = AB[(size_t)s * 512 + c] + AB[(size_t)d * 512 + 256 + c] + sb[c];
#pragma unroll
        for (int k = 0; k < 16; k++) v = fmaf(sea[i][k], sWc[k * H + c], v);
#pragma unroll
        for (int k = 0; k < 4; k++) v = fmaf(sxl[i][k], sWd[k * H + c], v);
        h[(size_t)e * H + c] = v;
    }
}

// ---------------- BN coefficient computation (reads then self-zeroes acc) ------
__global__ void bn_coef_kernel(float* __restrict__ acc,
                               const float* __restrict__ gamma, const float* __restrict__ beta,
                               float* __restrict__ scale, float* __restrict__ shift, int M)
{
    int c = threadIdx.x;
    float a0 = acc[c], a1 = acc[H + c];
    acc[c] = 0.f;
    acc[H + c] = 0.f;
    double mu = (double)a0 / (double)M;
    double var = (double)a1 / (double)M - mu * mu;
    float inv = rsqrtf((float)var + 1e-5f);
    float sc = gamma[c] * inv;
    scale[c] = sc;
    shift[c] = beta[c] - (float)mu * sc;
}

// ---------------- fused GENConv aggregation (CSR gather, fp16 out) -------------
#define RPB 8
__global__ __launch_bounds__(256) void gen_aggr_kernel(
    const float* __restrict__ x, const float* __restrict__ nbg, const float* __restrict__ ebg,
    const float* __restrict__ Wnb, const float* __restrict__ bnb,
    const float* __restrict__ Web, const float* __restrict__ beb,
    const float* __restrict__ bnscale, const float* __restrict__ bnshift,
    const int* __restrict__ src, const int* __restrict__ rowptr, const int* __restrict__ eidx,
    __half* __restrict__ aout, int E, int use_bn)
{
    __shared__ float sWn[4 * H], sWe[4 * H], sbn[H], sbe[H];
    int tid = threadIdx.x;
    for (int i = tid; i < 4 * H; i += 256) { sWn[i] = Wnb[i]; sWe[i] = Web[i]; }
    sbn[tid] = bnb[tid];
    sbe[tid] = beb[tid];
    __syncthreads();
    int c = tid;
    float sc = 1.f, sh = 0.f;
    if (use_bn) { sc = bnscale[c]; sh = bnshift[c]; }
    int d0 = blockIdx.x * RPB;
#pragma unroll
    for (int rr = 0; rr < RPB; rr++) {
        int d = d0 + rr;
        if (d >= E) break;
        int beg = rowptr[d], end = rowptr[d + 1];
        float se = 0.f, sw = 0.f, m0 = 0.f;
        for (int p = beg; p < end; p++) {
            int e = eidx[p];
            int s = src[e];
            float4 nv = *(const float4*)(nbg + (size_t)s * 4);
            float4 ev4 = *(const float4*)(ebg + (size_t)e * 4);
            float nbv = sbn[c];
            nbv = fmaf(nv.x, sWn[c], nbv);
            nbv = fmaf(nv.y, sWn[H + c], nbv);
            nbv = fmaf(nv.z, sWn[2 * H + c], nbv);
            nbv = fmaf(nv.w, sWn[3 * H + c], nbv);
            float ebv = sbe[c];
            ebv = fmaf(ev4.x, sWe[c], ebv);
            ebv = fmaf(ev4.y, sWe[H + c], ebv);
            ebv = fmaf(ev4.z, sWe[2 * H + c], ebv);
            ebv = fmaf(ev4.w, sWe[3 * H + c], ebv);
            float xv = x[(size_t)s * H + c];
            if (use_bn) xv = fmaxf(fmaf(xv, sc, sh), 0.f);
            float mv = fmaxf(xv + nbv + ebv, 0.f) + 1e-7f;
            if (p == beg) {
                m0 = mv;
                se = 1.f;
                sw = mv;
            } else {
                float dmv = fminf(fmaxf(mv - m0, -80.f), 80.f);
                float ee = __expf(dmv);
                se += ee;
                sw = fmaf(ee, mv, sw);
            }
        }
        float xv = x[(size_t)d * H + c];
        if (use_bn) xv = fmaxf(fmaf(xv, sc, sh), 0.f);
        float v = xv + __fdividef(sw, se + 1e-16f);
        aout[(size_t)d * H + c] = __float2half(v);
    }
}

// ---------------- fused node gather + graph pool (BN fused) --------------------
__global__ void node_pool_kernel(const float* __restrict__ h,
                                 const float* __restrict__ bnscale,
                                 const float* __restrict__ bnshift,
                                 const int* __restrict__ rowptr, const int* __restrict__ eidx,
                                 const int* __restrict__ batch,
                                 float* __restrict__ gsum, float* __restrict__ cnt)
{
    int n = blockIdx.x, c = threadIdx.x;
    float sc = bnscale[c], sh = bnshift[c];
    int beg = rowptr[n], end = rowptr[n + 1];
    float acc = 0.f;
    for (int p = beg; p < end; p++) {
        int e = eidx[p];
        acc += fmaf(h[(size_t)e * H + c], sc, sh);
    }
    int b = batch[n];
    atomicAdd(gsum + (size_t)b * H + c, acc);
    if (c == 0) atomicAdd(&cnt[b], 1.0f);
}

__global__ void predict_kernel(const float* __restrict__ gsum, const float* __restrict__ cnt,
                               const float* __restrict__ Wp, const float* __restrict__ bp,
                               float* __restrict__ out)
{
    int g = blockIdx.x, c = threadIdx.x;
    float v = gsum[(size_t)g * H + c] * Wp[c];
    __shared__ float red[8];
#pragma unroll
    for (int o = 16; o > 0; o >>= 1) v += __shfl_down_sync(0xffffffffu, v, o);
    if ((c & 31) == 0) red[c >> 5] = v;
    __syncthreads();
    if (c == 0) {
        float t = 0.f;
#pragma unroll
        for (int i = 0; i < 8; i++) t += red[i];
        out[g] = t / fmaxf(cnt[g], 1.0f) + bp[0];
    }
}

// -------------------------------------------------------------------------------
static void* symA(const void* sym)
{
    void* p = nullptr;
    cudaGetSymbolAddress(&p, sym);
    return p;
}

static void build_csr(const int* dst, int n, int E, int* deg, int* blk,
                      int* rowptr, int* cursor, int* eidx)
{
    int nb = (n + 255) / 256;
    zero_int_kernel<<<nb, 256>>>(deg, n);
    hist_kernel<<<(E + 255) / 256, 256>>>(dst, deg, E);
    scan_block_sums<<<nb, 256>>>(deg, blk, n);
    scan_single_block<<<1, 1024>>>(blk, nb);
    scan_final<<<nb, 256>>>(deg, blk, rowptr, cursor, n, E);
    fill_csr_kernel<<<(E + 255) / 256, 256>>>(dst, cursor, eidx, E);
}

extern "C" void kernel_launch(void* const* d_in, const int* in_sizes, int n_in,
                              void* d_out, int out_size)
{
    const float* x_g       = (const float*)d_in[0];
    const float* ea_g      = (const float*)d_in[1];
    const float* x_lg      = (const float*)d_in[2];
    const float* edb       = (const float*)d_in[3];
    const float* ea_lg     = (const float*)d_in[4];
    const float* W_enc     = (const float*)d_in[5];
    const float* b_enc     = (const float*)d_in[6];
    const float* W_msg     = (const float*)d_in[7];
    const float* b_msg     = (const float*)d_in[8];
    const float* Wg_nb     = (const float*)d_in[9];
    const float* bg_nb     = (const float*)d_in[10];
    const float* Wg_eb     = (const float*)d_in[11];
    const float* bg_eb     = (const float*)d_in[12];
    const float* Wl_nb     = (const float*)d_in[13];
    const float* bl_nb     = (const float*)d_in[14];
    const float* Wl_eb     = (const float*)d_in[15];
    const float* bl_eb     = (const float*)d_in[16];
    const float* W1        = (const float*)d_in[17];
    const float* b1        = (const float*)d_in[18];
    const float* W2        = (const float*)d_in[19];
    const float* b2        = (const float*)d_in[20];
    const float* bn_gamma  = (const float*)d_in[21];
    const float* bn_beta   = (const float*)d_in[22];
    const float* W_pred    = (const float*)d_in[23];
    const float* b_pred    = (const float*)d_in[24];
    const int*   eig       = (const int*)d_in[25];
    const int*   eil       = (const int*)d_in[26];
    const int*   batch     = (const int*)d_in[27];

    int N   = in_sizes[0] / 16;   // 20000
    int Eg  = in_sizes[1] / 16;   // 200000
    int Elg = in_sizes[4] / 4;    // 400000
    const int L = 4;

    cudaFuncSetAttribute(mma_gemm_kernel, cudaFuncAttributeMaxDynamicSharedMemorySize,
                         GEMM_SMEM);

    float* p_AB   = (float*)symA(g_AB);
    float* p_h    = (float*)symA(g_h);
    float* p_nbg  = (float*)symA(g_nbg);
    float* p_ebg  = (float*)symA(g_ebg);
    float* p_bnacc = (float*)symA(g_bnacc);
    float* p_bnsc = (float*)symA(g_bnscale);
    float* p_bnsh = (float*)symA(g_bnshift);
    float* p_gsum = (float*)symA(g_gsum);
    float* p_cnt  = (float*)symA(g_cnt);

    int* p_deg    = (int*)symA(g_deg);
    int* p_cursor = (int*)symA(g_cursor);
    int* p_blk    = (int*)symA(g_blk);
    int* p_rp_lg  = (int*)symA(g_rowptr_lg);
    int* p_ei_lg  = (int*)symA(g_eidx_lg);
    int* p_rp_g   = (int*)symA(g_rowptr_g);
    int* p_ei_g   = (int*)symA(g_eidx_g);

    __half* p_node = (__half*)symA(g_node);
    __half* p_act  = (__half*)symA(g_act);
    __half* p_hid  = (__half*)symA(g_hid);
    __half* p_wthi = (__half*)symA(g_wthi);
    __half* p_wtlo = (__half*)symA(g_wtlo);

    const int* src_g = eig;
    const int* dst_g = eig + Eg;
    const int* src_l = eil;
    const int* dst_l = eil + Elg;

    int mtE = (Eg + 127) / 128;   // 1563
    int mtN = (N + 127) / 128;    // 157

    // 1: weight prep; 2: encoder; 3-6: msg GEMM quarters (capture slots)
    tsplit_all_kernel<<<(1179648 + 255) / 256, 256>>>(W_msg, W1, W2, p_wthi, p_wtlo);
    enc_kernel<<<N, 256>>>(x_g, W_enc, b_enc, p_node);
    for (int t = 0; t < 4; t++) {
        dim3 grid(2, mtN);   // 2 n-tiles of 64 = 128 cols per launch
        mma_gemm_kernel<<<grid, 256, GEMM_SMEM>>>(
            p_node,
            p_wthi + OFF_WMSG + (size_t)t * 128 * 256,
            p_wtlo + OFF_WMSG + (size_t)t * 128 * 256,
            nullptr, nullptr, p_AB + t * 128, nullptr, nullptr, N, 512, 256, 0);
    }
    basis4_both_kernel<<<(Eg + Elg + 255) / 256, 256>>>(
        edb, Wg_nb, bg_nb, p_nbg, Eg,
        ea_lg, Wg_eb, bg_eb, p_ebg, Elg);
    msg_edge_kernel<<<(Eg + MEPB - 1) / MEPB, 256>>>(
        p_AB, ea_g, x_lg, W_msg + 512 * H, W_msg + 528 * H, b_msg,
        src_g, dst_g, p_h, Eg);
    build_csr(dst_l, Eg, Elg, p_deg, p_blk, p_rp_lg, p_cursor, p_ei_lg);
    build_csr(dst_g, N, Eg, p_deg, p_blk, p_rp_g, p_cursor, p_ei_g);

    cudaMemsetAsync(p_bnacc, 0, 2 * H * sizeof(float));

    // --- 4 GENConv layers ---
    for (int l = 0; l < L; l++) {
        int use_bn = (l > 0) ? 1 : 0;
        if (use_bn) {
            bn_coef_kernel<<<1, 256>>>(p_bnacc, bn_gamma + (l - 1) * H, bn_beta + (l - 1) * H,
                                       p_bnsc, p_bnsh, Eg);
        }
        gen_aggr_kernel<<<(Eg + RPB - 1) / RPB, 256>>>(
            p_h, p_nbg, p_ebg,
            Wl_nb + l * 4 * H, bl_nb + l * H,
            Wl_eb + l * 4 * H, bl_eb + l * H,
            p_bnsc, p_bnsh, src_l, p_rp_lg, p_ei_lg,
            p_act, Eg, use_bn);

        // GEMM1: hid = relu(act @ W1 + b1), fp16 out
        {
            dim3 grid(8, mtE);   // 8 n-tiles of 64
            mma_gemm_kernel<<<grid, 256, GEMM_SMEM>>>(
                p_act, p_wthi + OFF_W1T + l * 131072, p_wtlo + OFF_W1T + l * 131072,
                b1 + l * 512, nullptr, nullptr, p_hid, nullptr,
                Eg, 512, 256, 1 | 2 | 8);
        }
        // GEMM2: h = hid @ W2 + b2 (+ residual for l>0), fp32 out + fused BN stats
        {
            dim3 grid(4, mtE);   // 4 n-tiles of 64
            mma_gemm_kernel<<<grid, 256, GEMM_SMEM>>>(
                p_hid, p_wthi + OFF_W2T + l * 131072, p_wtlo + OFF_W2T + l * 131072,
                b2 + l * 256, (l > 0) ? p_h : nullptr, p_h, nullptr, p_bnacc,
                Eg, 256, 512, ((l > 0) ? (1 | 4) : 1) | 32);
        }
    }

    // --- final BN coefs + fused node gather/pool ---
    bn_coef_kernel<<<1, 256>>>(p_bnacc, bn_gamma + 3 * H, bn_beta + 3 * H, p_bnsc, p_bnsh, Eg);

    cudaMemsetAsync(p_gsum, 0, NGRAPH * H * sizeof(float));
    cudaMemsetAsync(p_cnt,  0, NGRAPH * sizeof(float));
    node_pool_kernel<<<N, 256>>>(p_h, p_bnsc, p_bnsh, p_rp_g, p_ei_g, batch, p_gsum, p_cnt);
    predict_kernel<<<NGRAPH, 256>>>(p_gsum, p_cnt, W_pred, b_pred, (float*)d_out);
}

// round 16
// speedup vs baseline: 1.0507x; 1.0507x over previous
#include <cuda_runtime.h>
#include <cuda_fp16.h>
#include <cstdint>

#define H 256
#define NGRAPH 128
#define MAXN   20224
#define MAXEG  200192
#define MAXELG 400128

// ---------------- scratch ----------------
__device__ float g_AB[(size_t)MAXN * 512];
__device__ float g_h[(size_t)MAXEG * H];
__device__ float g_nbg[(size_t)MAXEG * 4];
__device__ float g_ebg[(size_t)MAXELG * 4];
__device__ float g_bnacc[2 * H];
__device__ float g_bnscale[H];
__device__ float g_bnshift[H];
__device__ float g_gsum[NGRAPH * H];
__device__ float g_cnt[NGRAPH];

// CSR scratch
__device__ int g_deg[MAXEG];
__device__ int g_cursor[MAXEG];
__device__ int g_blk[1024];
__device__ int g_rowptr_lg[MAXEG + 1];
__device__ int g_eidx_lg[MAXELG];
__device__ int g_rowptr_g[MAXN + 1];
__device__ int g_eidx_g[MAXEG];

// fp16 activation buffers
__device__ __half g_node[(size_t)MAXN * H];
__device__ __half g_act[(size_t)MAXEG * H];
__device__ __half g_hid[(size_t)MAXEG * 2 * H];

// transposed/split fp16 weights arena
#define OFF_WMSG 0
#define OFF_W1T  (512 * 256)
#define OFF_W2T  (OFF_W1T + 4 * 131072)
#define WT_TOTAL (OFF_W2T + 4 * 131072)
__device__ __half g_wthi[WT_TOTAL];
__device__ __half g_wtlo[WT_TOTAL];

// ======================= helpers =======================
__device__ __forceinline__ uint32_t smem_u32(const void* p) {
    uint32_t a;
    asm("{ .reg .u64 t; cvta.to.shared.u64 t, %1; cvt.u32.u64 %0, t; }" : "=r"(a) : "l"(p));
    return a;
}
#define CP16(dst, src) \
    asm volatile("cp.async.cg.shared.global [%0], [%1], 16;" :: "r"(dst), "l"(src) : "memory")
#define CP16_CA(dst, src) \
    asm volatile("cp.async.ca.shared.global [%0], [%1], 16;" :: "r"(dst), "l"(src) : "memory")
#define CP_COMMIT() asm volatile("cp.async.commit_group;" ::: "memory")
#define CP_WAIT1()  asm volatile("cp.async.wait_group 1;" ::: "memory")
#define CP_WAIT0()  asm volatile("cp.async.wait_group 0;" ::: "memory")

__device__ __forceinline__ void ldm4(uint32_t (&r)[4], uint32_t addr) {
    asm volatile("ldmatrix.sync.aligned.m8n8.x4.shared.b16 {%0,%1,%2,%3}, [%4];"
                 : "=r"(r[0]), "=r"(r[1]), "=r"(r[2]), "=r"(r[3]) : "r"(addr));
}
__device__ __forceinline__ void mma_f16(float (&d)[4], const uint32_t (&a)[4], const uint32_t* b) {
    asm volatile(
        "mma.sync.aligned.m16n8k16.row.col.f32.f16.f16.f32 "
        "{%0,%1,%2,%3}, {%4,%5,%6,%7}, {%8,%9}, {%0,%1,%2,%3};"
        : "+f"(d[0]), "+f"(d[1]), "+f"(d[2]), "+f"(d[3])
        : "r"(a[0]), "r"(a[1]), "r"(a[2]), "r"(a[3]), "r"(b[0]), "r"(b[1]));
}

// ======================= CSR build kernels =======================
__global__ void zero_int_kernel(int* a, int n)
{
    int i = blockIdx.x * 256 + threadIdx.x;
    if (i < n) a[i] = 0;
}
__global__ void hist_kernel(const int* __restrict__ dst, int* __restrict__ deg, int E)
{
    int i = blockIdx.x * 256 + threadIdx.x;
    if (i < E) atomicAdd(&deg[dst[i]], 1);
}
__global__ void scan_block_sums(const int* __restrict__ deg, int* __restrict__ blk, int n)
{
    __shared__ int sd[256];
    int t = threadIdx.x;
    int i = blockIdx.x * 256 + t;
    sd[t] = (i < n) ? deg[i] : 0;
    __syncthreads();
    for (int o = 128; o > 0; o >>= 1) {
        if (t < o) sd[t] += sd[t + o];
        __syncthreads();
    }
    if (t == 0) blk[blockIdx.x] = sd[0];
}
__global__ void scan_single_block(int* blk, int nb)
{
    __shared__ int tmp[1024];
    int t = threadIdx.x;
    int v = (t < nb) ? blk[t] : 0;
    tmp[t] = v;
    __syncthreads();
    for (int o = 1; o < 1024; o <<= 1) {
        int u = (t >= o) ? tmp[t - o] : 0;
        __syncthreads();
        tmp[t] += u;
        __syncthreads();
    }
    if (t < nb) blk[t] = tmp[t] - v;
}
__global__ void scan_final(const int* __restrict__ deg, const int* __restrict__ blk,
                           int* __restrict__ rowptr, int* __restrict__ cursor, int n, int E)
{
    __shared__ int tmp[256];
    int t = threadIdx.x;
    int i = blockIdx.x * 256 + t;
    int v = (i < n) ? deg[i] : 0;
    tmp[t] = v;
    __syncthreads();
    for (int o = 1; o < 256; o <<= 1) {
        int u = (t >= o) ? tmp[t - o] : 0;
        __syncthreads();
        tmp[t] += u;
        __syncthreads();
    }
    int excl = tmp[t] - v + blk[blockIdx.x];
    if (i < n) { rowptr[i] = excl; cursor[i] = excl; }
    if (blockIdx.x == 0 && t == 0) rowptr[n] = E;
}
__global__ void fill_csr_kernel(const int* __restrict__ dst, int* __restrict__ cursor,
                                int* __restrict__ eidx, int E)
{
    int e = blockIdx.x * 256 + threadIdx.x;
    if (e < E) {
        int p = atomicAdd(&cursor[dst[e]], 1);
        eidx[p] = e;
    }
}

// ======================= mma.sync 2-term fp16 GEMM =======================
// CTA 128x128, 8 warps of 64x32, BK=32, 3 stages, 2 CTAs/SM. n-tile fast.
// flags: 1=bias, 2=relu, 4=residual fp32, 8=fp16 out, 32=BN stats
#define RB 80
#define TILE_B (128 * RB)
#define SO_A   0
#define SO_BHI (1 * TILE_B)
#define SO_BLO (2 * TILE_B)
#define STAGE_B (3 * TILE_B)
#define GEMM_SMEM (3 * STAGE_B)

__device__ __forceinline__ void load_stage(uint32_t sbase,
    const __half* __restrict__ A, const __half* __restrict__ B_hi,
    const __half* __restrict__ B_lo,
    int K, int m0, int n0, int k0, int tid)
{
#pragma unroll
    for (int i = 0; i < 2; i++) {
        int g = tid + i * 256;
        int row = g >> 2, ch = g & 3;
        uint32_t so = (uint32_t)row * RB + (uint32_t)ch * 16;
        size_t ao = (size_t)(m0 + row) * K + k0 + ch * 8;
        size_t bo = (size_t)(n0 + row) * K + k0 + ch * 8;
        CP16_CA(sbase + SO_A + so, A + ao);
        CP16(sbase + SO_BHI + so, B_hi + bo);
        CP16(sbase + SO_BLO + so, B_lo + bo);
    }
}

__global__ __launch_bounds__(256, 2) void mma_gemm_kernel(
    const __half* __restrict__ A,
    const __half* __restrict__ Bhi, const __half* __restrict__ Blo,
    const float* __restrict__ bias, const float* __restrict__ res,
    float* __restrict__ Cf, __half* __restrict__ Ch, float* __restrict__ bnacc,
    int M, int N, int K, int flags)
{
    extern __shared__ __align__(128) char smem[];
    uint32_t sb = smem_u32(smem);
    int tid = threadIdx.x;
    int wid = tid >> 5, lane = tid & 31;
    int m0 = blockIdx.y * 128, n0 = blockIdx.x * 128;
    int nk = K >> 5;

    load_stage(sb, A, Bhi, Blo, K, m0, n0, 0, tid);
    CP_COMMIT();
    load_stage(sb + STAGE_B, A, Bhi, Blo, K, m0, n0, 32, tid);
    CP_COMMIT();

    float acc[4][4][4];
#pragma unroll
    for (int i = 0; i < 4; i++)
#pragma unroll
        for (int j = 0; j < 4; j++)
#pragma unroll
            for (int q = 0; q < 4; q++) acc[i][j][q] = 0.f;

    int mo = (wid & 1) * 64, no = (wid >> 1) * 32;
    int a_row = mo + (lane & 15);
    int a_k8  = lane >> 4;
    int b_row = ((lane >> 4) << 3) + (lane & 7);
    int b_k8  = (lane >> 3) & 1;

    for (int k = 0; k < nk; k++) {
        if (k == nk - 1) { CP_WAIT0(); } else { CP_WAIT1(); }
        __syncthreads();
        uint32_t base = sb + (uint32_t)(k % 3) * STAGE_B;
        if (k + 2 < nk)
            load_stage(sb + (uint32_t)((k + 2) % 3) * STAGE_B, A, Bhi, Blo,
                       K, m0, n0, (k + 2) * 32, tid);
        CP_COMMIT();
#pragma unroll
        for (int k16 = 0; k16 < 2; k16++) {
            int kk8 = k16 * 2;
            uint32_t ah[4][4], bh[2][4], bl[2][4];
#pragma unroll
            for (int i = 0; i < 4; i++) {
                uint32_t aaddr = base + SO_A + (uint32_t)(a_row + i * 16) * RB
                               + (uint32_t)(kk8 + a_k8) * 16;
                ldm4(ah[i], aaddr);
            }
#pragma unroll
            for (int j = 0; j < 2; j++) {
                uint32_t baddr = base + SO_BHI + (uint32_t)(no + j * 16 + b_row) * RB
                               + (uint32_t)(kk8 + b_k8) * 16;
                ldm4(bh[j], baddr);
                ldm4(bl[j], baddr + (SO_BLO - SO_BHI));
            }
#pragma unroll
            for (int j = 0; j < 2; j++)
#pragma unroll
                for (int i = 0; i < 4; i++) {
                    mma_f16(acc[i][2 * j],     ah[i], &bh[j][0]);
                    mma_f16(acc[i][2 * j + 1], ah[i], &bh[j][2]);
                }
#pragma unroll
            for (int j = 0; j < 2; j++)
#pragma unroll
                for (int i = 0; i < 4; i++) {
                    mma_f16(acc[i][2 * j],     ah[i], &bl[j][0]);
                    mma_f16(acc[i][2 * j + 1], ah[i], &bl[j][2]);
                }
        }
    }

    // epilogue (+ optional fused BN statistics)
    float st[4][2], sq[4][2];
#pragma unroll
    for (int nb = 0; nb < 4; nb++) {
        st[nb][0] = st[nb][1] = 0.f;
        sq[nb][0] = sq[nb][1] = 0.f;
    }
#pragma unroll
    for (int i = 0; i < 4; i++) {
        int r0 = m0 + mo + i * 16 + (lane >> 2);
#pragma unroll
        for (int half = 0; half < 2; half++) {
            int r = r0 + half * 8;
            if (r >= M) continue;
#pragma unroll
            for (int nb = 0; nb < 4; nb++) {
                int col = n0 + no + nb * 8 + 2 * (lane & 3);
                float v0 = acc[i][nb][half * 2 + 0];
                float v1 = acc[i][nb][half * 2 + 1];
                if (flags & 1) { v0 += bias[col]; v1 += bias[col + 1]; }
                if (flags & 4) {
                    float2 t = *(const float2*)(res + (size_t)r * N + col);
                    v0 += t.x; v1 += t.y;
                }
                if (flags & 2) { v0 = fmaxf(v0, 0.f); v1 = fmaxf(v1, 0.f); }
                if (flags & 32) {
                    st[nb][0] += v0; sq[nb][0] = fmaf(v0, v0, sq[nb][0]);
                    st[nb][1] += v1; sq[nb][1] = fmaf(v1, v1, sq[nb][1]);
                }
                if (flags & 8) {
                    *(__half2*)(Ch + (size_t)r * N + col) =
                        __halves2half2(__float2half(v0), __float2half(v1));
                } else {
                    *(float2*)(Cf + (size_t)r * N + col) = make_float2(v0, v1);
                }
            }
        }
    }
    if (flags & 32) {
#pragma unroll
        for (int nb = 0; nb < 4; nb++)
#pragma unroll
            for (int w = 0; w < 2; w++) {
                float s = st[nb][w], q = sq[nb][w];
                s += __shfl_xor_sync(0xffffffffu, s, 4);
                q += __shfl_xor_sync(0xffffffffu, q, 4);
                s += __shfl_xor_sync(0xffffffffu, s, 8);
                q += __shfl_xor_sync(0xffffffffu, q, 8);
                s += __shfl_xor_sync(0xffffffffu, s, 16);
                q += __shfl_xor_sync(0xffffffffu, q, 16);
                if ((lane >> 2) == 0) {
                    int col = n0 + no + nb * 8 + 2 * (lane & 3) + w;
                    atomicAdd(&bnacc[col], s);
                    atomicAdd(&bnacc[N + col], q);
                }
            }
    }
}

// ---------------- ALL weight transpose+splits in one kernel --------------------
__global__ void tsplit_all_kernel(const float* __restrict__ Wmsg,
                                  const float* __restrict__ W1,
                                  const float* __restrict__ W2,
                                  __half* __restrict__ thi, __half* __restrict__ tlo)
{
    int idx = blockIdx.x * 256 + threadIdx.x;
    if (idx >= 1179648) return;
    float w;
    size_t dofs;
    if (idx < 131072) {
        int part = idx >> 16, e = idx & 65535;
        int k = e >> 8, n = e & 255;
        w = Wmsg[(size_t)part * 65536 + (size_t)k * 256 + n];
        dofs = (size_t)OFF_WMSG + part * 65536 + (size_t)n * 256 + k;
    } else if (idx < 655360) {
        int e = idx - 131072;
        int l = e >> 17, el = e & 131071;
        int k = el >> 9, n = el & 511;
        w = W1[(size_t)l * 131072 + (size_t)k * 512 + n];
        dofs = (size_t)OFF_W1T + (size_t)l * 131072 + (size_t)n * 256 + k;
    } else {
        int e = idx - 655360;
        int l = e >> 17, el = e & 131071;
        int k = el >> 8, n = el & 255;
        w = W2[(size_t)l * 131072 + (size_t)k * 256 + n];
        dofs = (size_t)OFF_W2T + (size_t)l * 131072 + (size_t)n * 512 + k;
    }
    __half hi = __float2half(w);
    __half lo = __float2half(w - __half2float(hi));
    thi[dofs] = hi;
    tlo[dofs] = lo;
}

// ---------------- node encoder (fp16 out) --------------------------------------
__global__ void enc_kernel(const float* __restrict__ xg, const float* __restrict__ W,
                           const float* __restrict__ b, __half* __restrict__ out)
{
    __shared__ float sx[16];
    int n = blockIdx.x, c = threadIdx.x;
    if (c < 16) sx[c] = xg[(size_t)n * 16 + c];
    __syncthreads();
    float v = b[c];
#pragma unroll
    for (int k = 0; k < 16; k++) v = fmaf(sx[k], W[k * H + c], v);
    out[(size_t)n * H + c] = __float2half(v);
}

// ---------------- combined tiny [.,4]@[4,4]+b projections ----------------------
__global__ void basis4_both_kernel(const float* __restrict__ in1, const float* __restrict__ W1,
                                   const float* __restrict__ b1v, float* __restrict__ out1, int E1,
                                   const float* __restrict__ in2, const float* __restrict__ W2,
                                   const float* __restrict__ b2v, float* __restrict__ out2, int E2)
{
    int e = blockIdx.x * blockDim.x + threadIdx.x;
    const float* in; const float* W; const float* b; float* out;
    if (e < E1) { in = in1; W = W1; b = b1v; out = out1; }
    else { e -= E1; if (e >= E2) return; in = in2; W = W2; b = b2v; out = out2; }
    float4 x = *(const float4*)(in + (size_t)e * 4);
    float o0 = b[0] + x.x * W[0] + x.y * W[4] + x.z * W[8]  + x.w * W[12];
    float o1 = b[1] + x.x * W[1] + x.y * W[5] + x.z * W[9]  + x.w * W[13];
    float o2 = b[2] + x.x * W[2] + x.y * W[6] + x.z * W[10] + x.w * W[14];
    float o3 = b[3] + x.x * W[3] + x.y * W[7] + x.z * W[11] + x.w * W[15];
    *(float4*)(out + (size_t)e * 4) = make_float4(o0, o1, o2, o3);
}

// ---------------- fused first-message ------------------------------------------
#define MEPB 16
__global__ __launch_bounds__(256) void msg_edge_kernel(
    const float* __restrict__ AB,
    const float* __restrict__ ea, const float* __restrict__ xlg,
    const float* __restrict__ Wc, const float* __restrict__ Wd,
    const float* __restrict__ bmsg,
    const int* __restrict__ srcg, const int* __restrict__ dstg,
    float* __restrict__ h, int Eg)
{
    __shared__ float sWc[16 * H];
    __shared__ float sWd[4 * H];
    __shared__ float sb[H];
    __shared__ float sea[MEPB][16];
    __shared__ float sxl[MEPB][4];
    int tid = threadIdx.x;
    for (int i = tid; i < 16 * H; i += 256) sWc[i] = Wc[i];
    for (int i = tid; i < 4 * H; i += 256) sWd[i] = Wd[i];
    sb[tid] = bmsg[tid];
    int e0 = blockIdx.x * MEPB;
    for (int i = tid; i < MEPB * 16; i += 256) {
        int e = e0 + i / 16;
        if (e < Eg) sea[i / 16][i % 16] = ea[(size_t)e * 16 + (i % 16)];
    }
    for (int i = tid; i < MEPB * 4; i += 256) {
        int e = e0 + i / 4;
        if (e < Eg) sxl[i / 4][i % 4] = xlg[(size_t)e * 4 + (i % 4)];
    }
    __syncthreads();
    int c = tid;
    for (int i = 0; i < MEPB; i++) {
        int e = e0 + i;
        if (e >= Eg) break;
        int s = srcg[e], d = dstg[e];
        float v = AB[(size_t)s * 512 + c] + AB[(size_t)d * 512 + 256 + c] + sb[c];
#pragma unroll
        for (int k = 0; k < 16; k++) v = fmaf(sea[i][k], sWc[k * H + c], v);
#pragma unroll
        for (int k = 0; k < 4; k++) v = fmaf(sxl[i][k], sWd[k * H + c], v);
        h[(size_t)e * H + c] = v;
    }
}

// ---------------- BN coefficient computation (reads then self-zeroes acc) ------
__global__ void bn_coef_kernel(float* __restrict__ acc,
                               const float* __restrict__ gamma, const float* __restrict__ beta,
                               float* __restrict__ scale, float* __restrict__ shift, int M)
{
    int c = threadIdx.x;
    float a0 = acc[c], a1 = acc[H + c];
    acc[c] = 0.f;
    acc[H + c] = 0.f;
    double mu = (double)a0 / (double)M;
    double var = (double)a1 / (double)M - mu * mu;
    float inv = rsqrtf((float)var + 1e-5f);
    float sc = gamma[c] * inv;
    scale[c] = sc;
    shift[c] = beta[c] - (float)mu * sc;
}

// ---------------- fused GENConv aggregation (CSR gather, fp16 out) -------------
#define RPB 8
__global__ __launch_bounds__(256) void gen_aggr_kernel(
    const float* __restrict__ x, const float* __restrict__ nbg, const float* __restrict__ ebg,
    const float* __restrict__ Wnb, const float* __restrict__ bnb,
    const float* __restrict__ Web, const float* __restrict__ beb,
    const float* __restrict__ bnscale, const float* __restrict__ bnshift,
    const int* __restrict__ src, const int* __restrict__ rowptr, const int* __restrict__ eidx,
    __half* __restrict__ aout, int E, int use_bn)
{
    __shared__ float sWn[4 * H], sWe[4 * H], sbn[H], sbe[H];
    int tid = threadIdx.x;
    for (int i = tid; i < 4 * H; i += 256) { sWn[i] = Wnb[i]; sWe[i] = Web[i]; }
    sbn[tid] = bnb[tid];
    sbe[tid] = beb[tid];
    __syncthreads();
    int c = tid;
    float sc = 1.f, sh = 0.f;
    if (use_bn) { sc = bnscale[c]; sh = bnshift[c]; }
    int d0 = blockIdx.x * RPB;
#pragma unroll
    for (int rr = 0; rr < RPB; rr++) {
        int d = d0 + rr;
        if (d >= E) break;
        int beg = rowptr[d], end = rowptr[d + 1];
        float se = 0.f, sw = 0.f, m0 = 0.f;
        for (int p = beg; p < end; p++) {
            int e = eidx[p];
            int s = src[e];
            float4 nv = *(const float4*)(nbg + (size_t)s * 4);
            float4 ev4 = *(const float4*)(ebg + (size_t)e * 4);
            float nbv = sbn[c];
            nbv = fmaf(nv.x, sWn[c], nbv);
            nbv = fmaf(nv.y, sWn[H + c], nbv);
            nbv = fmaf(nv.z, sWn[2 * H + c], nbv);
            nbv = fmaf(nv.w, sWn[3 * H + c], nbv);
            float ebv = sbe[c];
            ebv = fmaf(ev4.x, sWe[c], ebv);
            ebv = fmaf(ev4.y, sWe[H + c], ebv);
            ebv = fmaf(ev4.z, sWe[2 * H + c], ebv);
            ebv = fmaf(ev4.w, sWe[3 * H + c], ebv);
            float xv = x[(size_t)s * H + c];
            if (use_bn) xv = fmaxf(fmaf(xv, sc, sh), 0.f);
            float mv = fmaxf(xv + nbv + ebv, 0.f) + 1e-7f;
            if (p == beg) {
                m0 = mv;
                se = 1.f;
                sw = mv;
            } else {
                float dmv = fminf(fmaxf(mv - m0, -80.f), 80.f);
                float ee = __expf(dmv);
                se += ee;
                sw = fmaf(ee, mv, sw);
            }
        }
        float xv = x[(size_t)d * H + c];
        if (use_bn) xv = fmaxf(fmaf(xv, sc, sh), 0.f);
        float v = xv + __fdividef(sw, se + 1e-16f);
        aout[(size_t)d * H + c] = __float2half(v);
    }
}

// ---------------- fused node gather + graph pool (BN fused) --------------------
__global__ void node_pool_kernel(const float* __restrict__ h,
                                 const float* __restrict__ bnscale,
                                 const float* __restrict__ bnshift,
                                 const int* __restrict__ rowptr, const int* __restrict__ eidx,
                                 const int* __restrict__ batch,
                                 float* __restrict__ gsum, float* __restrict__ cnt)
{
    int n = blockIdx.x, c = threadIdx.x;
    float sc = bnscale[c], sh = bnshift[c];
    int beg = rowptr[n], end = rowptr[n + 1];
    float acc = 0.f;
    for (int p = beg; p < end; p++) {
        int e = eidx[p];
        acc += fmaf(h[(size_t)e * H + c], sc, sh);
    }
    int b = batch[n];
    atomicAdd(gsum + (size_t)b * H + c, acc);
    if (c == 0) atomicAdd(&cnt[b], 1.0f);
}

__global__ void predict_kernel(const float* __restrict__ gsum, const float* __restrict__ cnt,
                               const float* __restrict__ Wp, const float* __restrict__ bp,
                               float* __restrict__ out)
{
    int g = blockIdx.x, c = threadIdx.x;
    float v = gsum[(size_t)g * H + c] * Wp[c];
    __shared__ float red[8];
#pragma unroll
    for (int o = 16; o > 0; o >>= 1) v += __shfl_down_sync(0xffffffffu, v, o);
    if ((c & 31) == 0) red[c >> 5] = v;
    __syncthreads();
    if (c == 0) {
        float t = 0.f;
#pragma unroll
        for (int i = 0; i < 8; i++) t += red[i];
        out[g] = t / fmaxf(cnt[g], 1.0f) + bp[0];
    }
}

// -------------------------------------------------------------------------------
static void* symA(const void* sym)
{
    void* p = nullptr;
    cudaGetSymbolAddress(&p, sym);
    return p;
}

static void build_csr(const int* dst, int n, int E, int* deg, int* blk,
                      int* rowptr, int* cursor, int* eidx)
{
    int nb = (n + 255) / 256;
    zero_int_kernel<<<nb, 256>>>(deg, n);
    hist_kernel<<<(E + 255) / 256, 256>>>(dst, deg, E);
    scan_block_sums<<<nb, 256>>>(deg, blk, n);
    scan_single_block<<<1, 1024>>>(blk, nb);
    scan_final<<<nb, 256>>>(deg, blk, rowptr, cursor, n, E);
    fill_csr_kernel<<<(E + 255) / 256, 256>>>(dst, cursor, eidx, E);
}

extern "C" void kernel_launch(void* const* d_in, const int* in_sizes, int n_in,
                              void* d_out, int out_size)
{
    const float* x_g       = (const float*)d_in[0];
    const float* ea_g      = (const float*)d_in[1];
    const float* x_lg      = (const float*)d_in[2];
    const float* edb       = (const float*)d_in[3];
    const float* ea_lg     = (const float*)d_in[4];
    const float* W_enc     = (const float*)d_in[5];
    const float* b_enc     = (const float*)d_in[6];
    const float* W_msg     = (const float*)d_in[7];
    const float* b_msg     = (const float*)d_in[8];
    const float* Wg_nb     = (const float*)d_in[9];
    const float* bg_nb     = (const float*)d_in[10];
    const float* Wg_eb     = (const float*)d_in[11];
    const float* bg_eb     = (const float*)d_in[12];
    const float* Wl_nb     = (const float*)d_in[13];
    const float* bl_nb     = (const float*)d_in[14];
    const float* Wl_eb     = (const float*)d_in[15];
    const float* bl_eb     = (const float*)d_in[16];
    const float* W1        = (const float*)d_in[17];
    const float* b1        = (const float*)d_in[18];
    const float* W2        = (const float*)d_in[19];
    const float* b2        = (const float*)d_in[20];
    const float* bn_gamma  = (const float*)d_in[21];
    const float* bn_beta   = (const float*)d_in[22];
    const float* W_pred    = (const float*)d_in[23];
    const float* b_pred    = (const float*)d_in[24];
    const int*   eig       = (const int*)d_in[25];
    const int*   eil       = (const int*)d_in[26];
    const int*   batch     = (const int*)d_in[27];

    int N   = in_sizes[0] / 16;   // 20000
    int Eg  = in_sizes[1] / 16;   // 200000
    int Elg = in_sizes[4] / 4;    // 400000
    const int L = 4;

    cudaFuncSetAttribute(mma_gemm_kernel, cudaFuncAttributeMaxDynamicSharedMemorySize,
                         GEMM_SMEM);

    float* p_AB   = (float*)symA(g_AB);
    float* p_h    = (float*)symA(g_h);
    float* p_nbg  = (float*)symA(g_nbg);
    float* p_ebg  = (float*)symA(g_ebg);
    float* p_bnacc = (float*)symA(g_bnacc);
    float* p_bnsc = (float*)symA(g_bnscale);
    float* p_bnsh = (float*)symA(g_bnshift);
    float* p_gsum = (float*)symA(g_gsum);
    float* p_cnt  = (float*)symA(g_cnt);

    int* p_deg    = (int*)symA(g_deg);
    int* p_cursor = (int*)symA(g_cursor);
    int* p_blk    = (int*)symA(g_blk);
    int* p_rp_lg  = (int*)symA(g_rowptr_lg);
    int* p_ei_lg  = (int*)symA(g_eidx_lg);
    int* p_rp_g   = (int*)symA(g_rowptr_g);
    int* p_ei_g   = (int*)symA(g_eidx_g);

    __half* p_node = (__half*)symA(g_node);
    __half* p_act  = (__half*)symA(g_act);
    __half* p_hid  = (__half*)symA(g_hid);
    __half* p_wthi = (__half*)symA(g_wthi);
    __half* p_wtlo = (__half*)symA(g_wtlo);

    const int* src_g = eig;
    const int* dst_g = eig + Eg;
    const int* src_l = eil;
    const int* dst_l = eil + Elg;

    int mtE = (Eg + 127) / 128;   // 1563
    int mtN = (N + 127) / 128;    // 157

    // 1: weight prep; 2: encoder; 3: msg GEMM (single launch, n fast)
    tsplit_all_kernel<<<(1179648 + 255) / 256, 256>>>(W_msg, W1, W2, p_wthi, p_wtlo);
    enc_kernel<<<N, 256>>>(x_g, W_enc, b_enc, p_node);
    {
        dim3 grid(4, mtN);
        mma_gemm_kernel<<<grid, 256, GEMM_SMEM>>>(
            p_node, p_wthi + OFF_WMSG, p_wtlo + OFF_WMSG,
            nullptr, nullptr, p_AB, nullptr, nullptr, N, 512, 256, 0);
    }
    basis4_both_kernel<<<(Eg + Elg + 255) / 256, 256>>>(
        edb, Wg_nb, bg_nb, p_nbg, Eg,
        ea_lg, Wg_eb, bg_eb, p_ebg, Elg);
    msg_edge_kernel<<<(Eg + MEPB - 1) / MEPB, 256>>>(
        p_AB, ea_g, x_lg, W_msg + 512 * H, W_msg + 528 * H, b_msg,
        src_g, dst_g, p_h, Eg);
    build_csr(dst_l, Eg, Elg, p_deg, p_blk, p_rp_lg, p_cursor, p_ei_lg);
    build_csr(dst_g, N, Eg, p_deg, p_blk, p_rp_g, p_cursor, p_ei_g);

    cudaMemsetAsync(p_bnacc, 0, 2 * H * sizeof(float));

    // --- 4 GENConv layers ---
    for (int l = 0; l < L; l++) {
        int use_bn = (l > 0) ? 1 : 0;
        if (use_bn) {
            bn_coef_kernel<<<1, 256>>>(p_bnacc, bn_gamma + (l - 1) * H, bn_beta + (l - 1) * H,
                                       p_bnsc, p_bnsh, Eg);
        }
        gen_aggr_kernel<<<(Eg + RPB - 1) / RPB, 256>>>(
            p_h, p_nbg, p_ebg,
            Wl_nb + l * 4 * H, bl_nb + l * H,
            Wl_eb + l * 4 * H, bl_eb + l * H,
            p_bnsc, p_bnsh, src_l, p_rp_lg, p_ei_lg,
            p_act, Eg, use_bn);

        // GEMM1: hid = relu(act @ W1 + b1), fp16 out
        {
            dim3 grid(4, mtE);
            mma_gemm_kernel<<<grid, 256, GEMM_SMEM>>>(
                p_act, p_wthi + OFF_W1T + l * 131072, p_wtlo + OFF_W1T + l * 131072,
                b1 + l * 512, nullptr, nullptr, p_hid, nullptr,
                Eg, 512, 256, 1 | 2 | 8);
        }
        // GEMM2: h = hid @ W2 + b2 (+ residual for l>0), fp32 out + fused BN stats
        {
            dim3 grid(2, mtE);
            mma_gemm_kernel<<<grid, 256, GEMM_SMEM>>>(
                p_hid, p_wthi + OFF_W2T + l * 131072, p_wtlo + OFF_W2T + l * 131072,
                b2 + l * 256, (l > 0) ? p_h : nullptr, p_h, nullptr, p_bnacc,
                Eg, 256, 512, ((l > 0) ? (1 | 4) : 1) | 32);
        }
    }

    // --- final BN coefs + fused node gather/pool ---
    bn_coef_kernel<<<1, 256>>>(p_bnacc, bn_gamma + 3 * H, bn_beta + 3 * H, p_bnsc, p_bnsh, Eg);

    cudaMemsetAsync(p_gsum, 0, NGRAPH * H * sizeof(float));
    cudaMemsetAsync(p_cnt,  0, NGRAPH * sizeof(float));
    node_pool_kernel<<<N, 256>>>(p_h, p_bnsc, p_bnsh, p_rp_g, p_ei_g, batch, p_gsum, p_cnt);
    predict_kernel<<<NGRAPH, 256>>>(p_gsum, p_cnt, W_pred, b_pred, (float*)d_out);
}

// round 17
// speedup vs baseline: 1.1102x; 1.0566x over previous
#include <cuda_runtime.h>
#include <cuda_fp16.h>
#include <cstdint>

#define H 256
#define NGRAPH 128
#define MAXN   20224
#define MAXEG  200192
#define MAXELG 400128

// ---------------- scratch ----------------
__device__ float g_AB[(size_t)MAXN * 512];
__device__ float g_h[(size_t)MAXEG * H];
__device__ float g_nbg[(size_t)MAXEG * 4];
__device__ float g_ebg[(size_t)MAXELG * 4];
__device__ float g_bnacc[2 * H];
__device__ float g_bnscale[H];
__device__ float g_bnshift[H];
__device__ float g_gsum[NGRAPH * H];
__device__ float g_cnt[NGRAPH];

// CSR scratch
__device__ int g_deg[MAXEG];
__device__ int g_cursor[MAXEG];
__device__ int g_blk[1024];
__device__ int g_rowptr_lg[MAXEG + 1];
__device__ int g_eidx_lg[MAXELG];
__device__ int g_rowptr_g[MAXN + 1];
__device__ int g_eidx_g[MAXEG];

// fp16 activation buffers
__device__ __half g_node[(size_t)MAXN * H];
__device__ __half g_act[(size_t)MAXEG * H];
__device__ __half g_hid[(size_t)MAXEG * 2 * H];

// transposed/split fp16 weights arena
#define OFF_WMSG 0
#define OFF_W1T  (512 * 256)
#define OFF_W2T  (OFF_W1T + 4 * 131072)
#define WT_TOTAL (OFF_W2T + 4 * 131072)
__device__ __half g_wthi[WT_TOTAL];
__device__ __half g_wtlo[WT_TOTAL];

// ======================= helpers =======================
__device__ __forceinline__ uint32_t smem_u32(const void* p) {
    uint32_t a;
    asm("{ .reg .u64 t; cvta.to.shared.u64 t, %1; cvt.u32.u64 %0, t; }" : "=r"(a) : "l"(p));
    return a;
}
#define CP16(dst, src) \
    asm volatile("cp.async.cg.shared.global [%0], [%1], 16;" :: "r"(dst), "l"(src) : "memory")
#define CP16_CA(dst, src) \
    asm volatile("cp.async.ca.shared.global [%0], [%1], 16;" :: "r"(dst), "l"(src) : "memory")
#define CP_COMMIT() asm volatile("cp.async.commit_group;" ::: "memory")
#define CP_WAIT0()  asm volatile("cp.async.wait_group 0;" ::: "memory")

__device__ __forceinline__ void ldm4(uint32_t (&r)[4], uint32_t addr) {
    asm volatile("ldmatrix.sync.aligned.m8n8.x4.shared.b16 {%0,%1,%2,%3}, [%4];"
                 : "=r"(r[0]), "=r"(r[1]), "=r"(r[2]), "=r"(r[3]) : "r"(addr));
}
__device__ __forceinline__ void mma_f16(float (&d)[4], const uint32_t (&a)[4], const uint32_t* b) {
    asm volatile(
        "mma.sync.aligned.m16n8k16.row.col.f32.f16.f16.f32 "
        "{%0,%1,%2,%3}, {%4,%5,%6,%7}, {%8,%9}, {%0,%1,%2,%3};"
        : "+f"(d[0]), "+f"(d[1]), "+f"(d[2]), "+f"(d[3])
        : "r"(a[0]), "r"(a[1]), "r"(a[2]), "r"(a[3]), "r"(b[0]), "r"(b[1]));
}

// ======================= CSR build kernels =======================
__global__ void zero_int_kernel(int* a, int n)
{
    int i = blockIdx.x * 256 + threadIdx.x;
    if (i < n) a[i] = 0;
}
__global__ void hist_kernel(const int* __restrict__ dst, int* __restrict__ deg, int E)
{
    int i = blockIdx.x * 256 + threadIdx.x;
    if (i < E) atomicAdd(&deg[dst[i]], 1);
}
__global__ void scan_block_sums(const int* __restrict__ deg, int* __restrict__ blk, int n)
{
    __shared__ int sd[256];
    int t = threadIdx.x;
    int i = blockIdx.x * 256 + t;
    sd[t] = (i < n) ? deg[i] : 0;
    __syncthreads();
    for (int o = 128; o > 0; o >>= 1) {
        if (t < o) sd[t] += sd[t + o];
        __syncthreads();
    }
    if (t == 0) blk[blockIdx.x] = sd[0];
}
__global__ void scan_single_block(int* blk, int nb)
{
    __shared__ int tmp[1024];
    int t = threadIdx.x;
    int v = (t < nb) ? blk[t] : 0;
    tmp[t] = v;
    __syncthreads();
    for (int o = 1; o < 1024; o <<= 1) {
        int u = (t >= o) ? tmp[t - o] : 0;
        __syncthreads();
        tmp[t] += u;
        __syncthreads();
    }
    if (t < nb) blk[t] = tmp[t] - v;
}
__global__ void scan_final(const int* __restrict__ deg, const int* __restrict__ blk,
                           int* __restrict__ rowptr, int* __restrict__ cursor, int n, int E)
{
    __shared__ int tmp[256];
    int t = threadIdx.x;
    int i = blockIdx.x * 256 + t;
    int v = (i < n) ? deg[i] : 0;
    tmp[t] = v;
    __syncthreads();
    for (int o = 1; o < 256; o <<= 1) {
        int u = (t >= o) ? tmp[t - o] : 0;
        __syncthreads();
        tmp[t] += u;
        __syncthreads();
    }
    int excl = tmp[t] - v + blk[blockIdx.x];
    if (i < n) { rowptr[i] = excl; cursor[i] = excl; }
    if (blockIdx.x == 0 && t == 0) rowptr[n] = E;
}
__global__ void fill_csr_kernel(const int* __restrict__ dst, int* __restrict__ cursor,
                                int* __restrict__ eidx, int E)
{
    int e = blockIdx.x * 256 + threadIdx.x;
    if (e < E) {
        int p = atomicAdd(&cursor[dst[e]], 1);
        eidx[p] = e;
    }
}

// ======================= mma.sync 2-term fp16 GEMM =======================
// CTA 128x128, 8 warps of 64x32, BK=64, 2-stage double buffer, 2 CTAs/SM.
// Half the barrier/wait count of the BK=32 3-stage version.
// flags: 1=bias, 2=relu, 4=residual fp32, 8=fp16 out, 32=BN stats
#define RB 144
#define TILE_B (128 * RB)           // 18432
#define SO_A   0
#define SO_BHI (1 * TILE_B)
#define SO_BLO (2 * TILE_B)
#define STAGE_B (3 * TILE_B)        // 55296
#define GEMM_SMEM (2 * STAGE_B)     // 110592

__device__ __forceinline__ void load_stage(uint32_t sbase,
    const __half* __restrict__ A, const __half* __restrict__ B_hi,
    const __half* __restrict__ B_lo,
    int K, int m0, int n0, int k0, int tid)
{
#pragma unroll
    for (int i = 0; i < 4; i++) {
        int g = tid + i * 256;              // 0..1023: 128 rows x 8 chunks
        int row = g >> 3, ch = g & 7;
        uint32_t so = (uint32_t)row * RB + (uint32_t)ch * 16;
        size_t ao = (size_t)(m0 + row) * K + k0 + ch * 8;
        size_t bo = (size_t)(n0 + row) * K + k0 + ch * 8;
        CP16_CA(sbase + SO_A + so, A + ao);
        CP16(sbase + SO_BHI + so, B_hi + bo);
        CP16(sbase + SO_BLO + so, B_lo + bo);
    }
}

__global__ __launch_bounds__(256, 2) void mma_gemm_kernel(
    const __half* __restrict__ A,
    const __half* __restrict__ Bhi, const __half* __restrict__ Blo,
    const float* __restrict__ bias, const float* __restrict__ res,
    float* __restrict__ Cf, __half* __restrict__ Ch, float* __restrict__ bnacc,
    int M, int N, int K, int flags)
{
    extern __shared__ __align__(128) char smem[];
    uint32_t sb = smem_u32(smem);
    int tid = threadIdx.x;
    int wid = tid >> 5, lane = tid & 31;
    int m0 = blockIdx.y * 128, n0 = blockIdx.x * 128;
    int nk = K >> 6;

    load_stage(sb, A, Bhi, Blo, K, m0, n0, 0, tid);
    CP_COMMIT();

    float acc[4][4][4];
#pragma unroll
    for (int i = 0; i < 4; i++)
#pragma unroll
        for (int j = 0; j < 4; j++)
#pragma unroll
            for (int q = 0; q < 4; q++) acc[i][j][q] = 0.f;

    int mo = (wid & 1) * 64, no = (wid >> 1) * 32;
    int a_row = mo + (lane & 15);
    int a_k8  = lane >> 4;
    int b_row = ((lane >> 4) << 3) + (lane & 7);
    int b_k8  = (lane >> 3) & 1;

    for (int k = 0; k < nk; k++) {
        CP_WAIT0();
        __syncthreads();
        uint32_t base = sb + (uint32_t)(k & 1) * STAGE_B;
        if (k + 1 < nk) {
            load_stage(sb + (uint32_t)((k + 1) & 1) * STAGE_B, A, Bhi, Blo,
                       K, m0, n0, (k + 1) * 64, tid);
            CP_COMMIT();
        }
#pragma unroll
        for (int k16 = 0; k16 < 4; k16++) {
            int kk8 = k16 * 2;
            uint32_t ah[4][4], bh[2][4], bl[2][4];
#pragma unroll
            for (int i = 0; i < 4; i++) {
                uint32_t aaddr = base + SO_A + (uint32_t)(a_row + i * 16) * RB
                               + (uint32_t)(kk8 + a_k8) * 16;
                ldm4(ah[i], aaddr);
            }
#pragma unroll
            for (int j = 0; j < 2; j++) {
                uint32_t baddr = base + SO_BHI + (uint32_t)(no + j * 16 + b_row) * RB
                               + (uint32_t)(kk8 + b_k8) * 16;
                ldm4(bh[j], baddr);
                ldm4(bl[j], baddr + (SO_BLO - SO_BHI));
            }
#pragma unroll
            for (int j = 0; j < 2; j++)
#pragma unroll
                for (int i = 0; i < 4; i++) {
                    mma_f16(acc[i][2 * j],     ah[i], &bh[j][0]);
                    mma_f16(acc[i][2 * j + 1], ah[i], &bh[j][2]);
                }
#pragma unroll
            for (int j = 0; j < 2; j++)
#pragma unroll
                for (int i = 0; i < 4; i++) {
                    mma_f16(acc[i][2 * j],     ah[i], &bl[j][0]);
                    mma_f16(acc[i][2 * j + 1], ah[i], &bl[j][2]);
                }
        }
    }

    // epilogue (+ optional fused BN statistics)
    float st[4][2], sq[4][2];
#pragma unroll
    for (int nb = 0; nb < 4; nb++) {
        st[nb][0] = st[nb][1] = 0.f;
        sq[nb][0] = sq[nb][1] = 0.f;
    }
#pragma unroll
    for (int i = 0; i < 4; i++) {
        int r0 = m0 + mo + i * 16 + (lane >> 2);
#pragma unroll
        for (int half = 0; half < 2; half++) {
            int r = r0 + half * 8;
            if (r >= M) continue;
#pragma unroll
            for (int nb = 0; nb < 4; nb++) {
                int col = n0 + no + nb * 8 + 2 * (lane & 3);
                float v0 = acc[i][nb][half * 2 + 0];
                float v1 = acc[i][nb][half * 2 + 1];
                if (flags & 1) { v0 += bias[col]; v1 += bias[col + 1]; }
                if (flags & 4) {
                    float2 t = *(const float2*)(res + (size_t)r * N + col);
                    v0 += t.x; v1 += t.y;
                }
                if (flags & 2) { v0 = fmaxf(v0, 0.f); v1 = fmaxf(v1, 0.f); }
                if (flags & 32) {
                    st[nb][0] += v0; sq[nb][0] = fmaf(v0, v0, sq[nb][0]);
                    st[nb][1] += v1; sq[nb][1] = fmaf(v1, v1, sq[nb][1]);
                }
                if (flags & 8) {
                    *(__half2*)(Ch + (size_t)r * N + col) =
                        __halves2half2(__float2half(v0), __float2half(v1));
                } else {
                    *(float2*)(Cf + (size_t)r * N + col) = make_float2(v0, v1);
                }
            }
        }
    }
    if (flags & 32) {
#pragma unroll
        for (int nb = 0; nb < 4; nb++)
#pragma unroll
            for (int w = 0; w < 2; w++) {
                float s = st[nb][w], q = sq[nb][w];
                s += __shfl_xor_sync(0xffffffffu, s, 4);
                q += __shfl_xor_sync(0xffffffffu, q, 4);
                s += __shfl_xor_sync(0xffffffffu, s, 8);
                q += __shfl_xor_sync(0xffffffffu, q, 8);
                s += __shfl_xor_sync(0xffffffffu, s, 16);
                q += __shfl_xor_sync(0xffffffffu, q, 16);
                if ((lane >> 2) == 0) {
                    int col = n0 + no + nb * 8 + 2 * (lane & 3) + w;
                    atomicAdd(&bnacc[col], s);
                    atomicAdd(&bnacc[N + col], q);
                }
            }
    }
}

// ---------------- ALL weight transpose+splits in one kernel --------------------
__global__ void tsplit_all_kernel(const float* __restrict__ Wmsg,
                                  const float* __restrict__ W1,
                                  const float* __restrict__ W2,
                                  __half* __restrict__ thi, __half* __restrict__ tlo)
{
    int idx = blockIdx.x * 256 + threadIdx.x;
    if (idx >= 1179648) return;
    float w;
    size_t dofs;
    if (idx < 131072) {
        int part = idx >> 16, e = idx & 65535;
        int k = e >> 8, n = e & 255;
        w = Wmsg[(size_t)part * 65536 + (size_t)k * 256 + n];
        dofs = (size_t)OFF_WMSG + part * 65536 + (size_t)n * 256 + k;
    } else if (idx < 655360) {
        int e = idx - 131072;
        int l = e >> 17, el = e & 131071;
        int k = el >> 9, n = el & 511;
        w = W1[(size_t)l * 131072 + (size_t)k * 512 + n];
        dofs = (size_t)OFF_W1T + (size_t)l * 131072 + (size_t)n * 256 + k;
    } else {
        int e = idx - 655360;
        int l = e >> 17, el = e & 131071;
        int k = el >> 8, n = el & 255;
        w = W2[(size_t)l * 131072 + (size_t)k * 256 + n];
        dofs = (size_t)OFF_W2T + (size_t)l * 131072 + (size_t)n * 512 + k;
    }
    __half hi = __float2half(w);
    __half lo = __float2half(w - __half2float(hi));
    thi[dofs] = hi;
    tlo[dofs] = lo;
}

// ---------------- node encoder (fp16 out) --------------------------------------
__global__ void enc_kernel(const float* __restrict__ xg, const float* __restrict__ W,
                           const float* __restrict__ b, __half* __restrict__ out)
{
    __shared__ float sx[16];
    int n = blockIdx.x, c = threadIdx.x;
    if (c < 16) sx[c] = xg[(size_t)n * 16 + c];
    __syncthreads();
    float v = b[c];
#pragma unroll
    for (int k = 0; k < 16; k++) v = fmaf(sx[k], W[k * H + c], v);
    out[(size_t)n * H + c] = __float2half(v);
}

// ---------------- combined tiny [.,4]@[4,4]+b projections ----------------------
__global__ void basis4_both_kernel(const float* __restrict__ in1, const float* __restrict__ W1,
                                   const float* __restrict__ b1v, float* __restrict__ out1, int E1,
                                   const float* __restrict__ in2, const float* __restrict__ W2,
                                   const float* __restrict__ b2v, float* __restrict__ out2, int E2)
{
    int e = blockIdx.x * blockDim.x + threadIdx.x;
    const float* in; const float* W; const float* b; float* out;
    if (e < E1) { in = in1; W = W1; b = b1v; out = out1; }
    else { e -= E1; if (e >= E2) return; in = in2; W = W2; b = b2v; out = out2; }
    float4 x = *(const float4*)(in + (size_t)e * 4);
    float o0 = b[0] + x.x * W[0] + x.y * W[4] + x.z * W[8]  + x.w * W[12];
    float o1 = b[1] + x.x * W[1] + x.y * W[5] + x.z * W[9]  + x.w * W[13];
    float o2 = b[2] + x.x * W[2] + x.y * W[6] + x.z * W[10] + x.w * W[14];
    float o3 = b[3] + x.x * W[3] + x.y * W[7] + x.z * W[11] + x.w * W[15];
    *(float4*)(out + (size_t)e * 4) = make_float4(o0, o1, o2, o3);
}

// ---------------- fused first-message ------------------------------------------
#define MEPB 16
__global__ __launch_bounds__(256) void msg_edge_kernel(
    const float* __restrict__ AB,
    const float* __restrict__ ea, const float* __restrict__ xlg,
    const float* __restrict__ Wc, const float* __restrict__ Wd,
    const float* __restrict__ bmsg,
    const int* __restrict__ srcg, const int* __restrict__ dstg,
    float* __restrict__ h, int Eg)
{
    __shared__ float sWc[16 * H];
    __shared__ float sWd[4 * H];
    __shared__ float sb[H];
    __shared__ float sea[MEPB][16];
    __shared__ float sxl[MEPB][4];
    int tid = threadIdx.x;
    for (int i = tid; i < 16 * H; i += 256) sWc[i] = Wc[i];
    for (int i = tid; i < 4 * H; i += 256) sWd[i] = Wd[i];
    sb[tid] = bmsg[tid];
    int e0 = blockIdx.x * MEPB;
    for (int i = tid; i < MEPB * 16; i += 256) {
        int e = e0 + i / 16;
        if (e < Eg) sea[i / 16][i % 16] = ea[(size_t)e * 16 + (i % 16)];
    }
    for (int i = tid; i < MEPB * 4; i += 256) {
        int e = e0 + i / 4;
        if (e < Eg) sxl[i / 4][i % 4] = xlg[(size_t)e * 4 + (i % 4)];
    }
    __syncthreads();
    int c = tid;
    for (int i = 0; i < MEPB; i++) {
        int e = e0 + i;
        if (e >= Eg) break;
        int s = srcg[e], d = dstg[e];
        float v = AB[(size_t)s * 512 + c] + AB[(size_t)d * 512 + 256 + c] + sb[c];
#pragma unroll
        for (int k = 0; k < 16; k++) v = fmaf(sea[i][k], sWc[k * H + c], v);
#pragma unroll
        for (int k = 0; k < 4; k++) v = fmaf(sxl[i][k], sWd[k * H + c], v);
        h[(size_t)e * H + c] = v;
    }
}

// ---------------- BN coefficient computation (reads then self-zeroes acc) ------
__global__ void bn_coef_kernel(float* __restrict__ acc,
                               const float* __restrict__ gamma, const float* __restrict__ beta,
                               float* __restrict__ scale, float* __restrict__ shift, int M)
{
    int c = threadIdx.x;
    float a0 = acc[c], a1 = acc[H + c];
    acc[c] = 0.f;
    acc[H + c] = 0.f;
    double mu = (double)a0 / (double)M;
    double var = (double)a1 / (double)M - mu * mu;
    float inv = rsqrtf((float)var + 1e-5f);
    float sc = gamma[c] * inv;
    scale[c] = sc;
    shift[c] = beta[c] - (float)mu * sc;
}

// ---------------- fused GENConv aggregation (CSR gather, fp16 out) -------------
#define RPB 8
__global__ __launch_bounds__(256) void gen_aggr_kernel(
    const float* __restrict__ x, const float* __restrict__ nbg, const float* __restrict__ ebg,
    const float* __restrict__ Wnb, const float* __restrict__ bnb,
    const float* __restrict__ Web, const float* __restrict__ beb,
    const float* __restrict__ bnscale, const float* __restrict__ bnshift,
    const int* __restrict__ src, const int* __restrict__ rowptr, const int* __restrict__ eidx,
    __half* __restrict__ aout, int E, int use_bn)
{
    __shared__ float sWn[4 * H], sWe[4 * H], sbn[H], sbe[H];
    int tid = threadIdx.x;
    for (int i = tid; i < 4 * H; i += 256) { sWn[i] = Wnb[i]; sWe[i] = Web[i]; }
    sbn[tid] = bnb[tid];
    sbe[tid] = beb[tid];
    __syncthreads();
    int c = tid;
    float sc = 1.f, sh = 0.f;
    if (use_bn) { sc = bnscale[c]; sh = bnshift[c]; }
    int d0 = blockIdx.x * RPB;
#pragma unroll
    for (int rr = 0; rr < RPB; rr++) {
        int d = d0 + rr;
        if (d >= E) break;
        int beg = rowptr[d], end = rowptr[d + 1];
        float se = 0.f, sw = 0.f, m0 = 0.f;
        for (int p = beg; p < end; p++) {
            int e = eidx[p];
            int s = src[e];
            float4 nv = *(const float4*)(nbg + (size_t)s * 4);
            float4 ev4 = *(const float4*)(ebg + (size_t)e * 4);
            float nbv = sbn[c];
            nbv = fmaf(nv.x, sWn[c], nbv);
            nbv = fmaf(nv.y, sWn[H + c], nbv);
            nbv = fmaf(nv.z, sWn[2 * H + c], nbv);
            nbv = fmaf(nv.w, sWn[3 * H + c], nbv);
            float ebv = sbe[c];
            ebv = fmaf(ev4.x, sWe[c], ebv);
            ebv = fmaf(ev4.y, sWe[H + c], ebv);
            ebv = fmaf(ev4.z, sWe[2 * H + c], ebv);
            ebv = fmaf(ev4.w, sWe[3 * H + c], ebv);
            float xv = x[(size_t)s * H + c];
            if (use_bn) xv = fmaxf(fmaf(xv, sc, sh), 0.f);
            float mv = fmaxf(xv + nbv + ebv, 0.f) + 1e-7f;
            if (p == beg) {
                m0 = mv;
                se = 1.f;
                sw = mv;
            } else {
                float dmv = fminf(fmaxf(mv - m0, -80.f), 80.f);
                float ee = __expf(dmv);
                se += ee;
                sw = fmaf(ee, mv, sw);
            }
        }
        float xv = x[(size_t)d * H + c];
        if (use_bn) xv = fmaxf(fmaf(xv, sc, sh), 0.f);
        float v = xv + __fdividef(sw, se + 1e-16f);
        aout[(size_t)d * H + c] = __float2half(v);
    }
}

// ---------------- fused node gather + graph pool (BN fused) --------------------
__global__ void node_pool_kernel(const float* __restrict__ h,
                                 const float* __restrict__ bnscale,
                                 const float* __restrict__ bnshift,
                                 const int* __restrict__ rowptr, const int* __restrict__ eidx,
                                 const int* __restrict__ batch,
                                 float* __restrict__ gsum, float* __restrict__ cnt)
{
    int n = blockIdx.x, c = threadIdx.x;
    float sc = bnscale[c], sh = bnshift[c];
    int beg = rowptr[n], end = rowptr[n + 1];
    float acc = 0.f;
    for (int p = beg; p < end; p++) {
        int e = eidx[p];
        acc += fmaf(h[(size_t)e * H + c], sc, sh);
    }
    int b = batch[n];
    atomicAdd(gsum + (size_t)b * H + c, acc);
    if (c == 0) atomicAdd(&cnt[b], 1.0f);
}

__global__ void predict_kernel(const float* __restrict__ gsum, const float* __restrict__ cnt,
                               const float* __restrict__ Wp, const float* __restrict__ bp,
                               float* __restrict__ out)
{
    int g = blockIdx.x, c = threadIdx.x;
    float v = gsum[(size_t)g * H + c] * Wp[c];
    __shared__ float red[8];
#pragma unroll
    for (int o = 16; o > 0; o >>= 1) v += __shfl_down_sync(0xffffffffu, v, o);
    if ((c & 31) == 0) red[c >> 5] = v;
    __syncthreads();
    if (c == 0) {
        float t = 0.f;
#pragma unroll
        for (int i = 0; i < 8; i++) t += red[i];
        out[g] = t / fmaxf(cnt[g], 1.0f) + bp[0];
    }
}

// -------------------------------------------------------------------------------
static void* symA(const void* sym)
{
    void* p = nullptr;
    cudaGetSymbolAddress(&p, sym);
    return p;
}

static void build_csr(const int* dst, int n, int E, int* deg, int* blk,
                      int* rowptr, int* cursor, int* eidx)
{
    int nb = (n + 255) / 256;
    zero_int_kernel<<<nb, 256>>>(deg, n);
    hist_kernel<<<(E + 255) / 256, 256>>>(dst, deg, E);
    scan_block_sums<<<nb, 256>>>(deg, blk, n);
    scan_single_block<<<1, 1024>>>(blk, nb);
    scan_final<<<nb, 256>>>(deg, blk, rowptr, cursor, n, E);
    fill_csr_kernel<<<(E + 255) / 256, 256>>>(dst, cursor, eidx, E);
}

extern "C" void kernel_launch(void* const* d_in, const int* in_sizes, int n_in,
                              void* d_out, int out_size)
{
    const float* x_g       = (const float*)d_in[0];
    const float* ea_g      = (const float*)d_in[1];
    const float* x_lg      = (const float*)d_in[2];
    const float* edb       = (const float*)d_in[3];
    const float* ea_lg     = (const float*)d_in[4];
    const float* W_enc     = (const float*)d_in[5];
    const float* b_enc     = (const float*)d_in[6];
    const float* W_msg     = (const float*)d_in[7];
    const float* b_msg     = (const float*)d_in[8];
    const float* Wg_nb     = (const float*)d_in[9];
    const float* bg_nb     = (const float*)d_in[10];
    const float* Wg_eb     = (const float*)d_in[11];
    const float* bg_eb     = (const float*)d_in[12];
    const float* Wl_nb     = (const float*)d_in[13];
    const float* bl_nb     = (const float*)d_in[14];
    const float* Wl_eb     = (const float*)d_in[15];
    const float* bl_eb     = (const float*)d_in[16];
    const float* W1        = (const float*)d_in[17];
    const float* b1        = (const float*)d_in[18];
    const float* W2        = (const float*)d_in[19];
    const float* b2        = (const float*)d_in[20];
    const float* bn_gamma  = (const float*)d_in[21];
    const float* bn_beta   = (const float*)d_in[22];
    const float* W_pred    = (const float*)d_in[23];
    const float* b_pred    = (const float*)d_in[24];
    const int*   eig       = (const int*)d_in[25];
    const int*   eil       = (const int*)d_in[26];
    const int*   batch     = (const int*)d_in[27];

    int N   = in_sizes[0] / 16;   // 20000
    int Eg  = in_sizes[1] / 16;   // 200000
    int Elg = in_sizes[4] / 4;    // 400000
    const int L = 4;

    cudaFuncSetAttribute(mma_gemm_kernel, cudaFuncAttributeMaxDynamicSharedMemorySize,
                         GEMM_SMEM);

    float* p_AB   = (float*)symA(g_AB);
    float* p_h    = (float*)symA(g_h);
    float* p_nbg  = (float*)symA(g_nbg);
    float* p_ebg  = (float*)symA(g_ebg);
    float* p_bnacc = (float*)symA(g_bnacc);
    float* p_bnsc = (float*)symA(g_bnscale);
    float* p_bnsh = (float*)symA(g_bnshift);
    float* p_gsum = (float*)symA(g_gsum);
    float* p_cnt  = (float*)symA(g_cnt);

    int* p_deg    = (int*)symA(g_deg);
    int* p_cursor = (int*)symA(g_cursor);
    int* p_blk    = (int*)symA(g_blk);
    int* p_rp_lg  = (int*)symA(g_rowptr_lg);
    int* p_ei_lg  = (int*)symA(g_eidx_lg);
    int* p_rp_g   = (int*)symA(g_rowptr_g);
    int* p_ei_g   = (int*)symA(g_eidx_g);

    __half* p_node = (__half*)symA(g_node);
    __half* p_act  = (__half*)symA(g_act);
    __half* p_hid  = (__half*)symA(g_hid);
    __half* p_wthi = (__half*)symA(g_wthi);
    __half* p_wtlo = (__half*)symA(g_wtlo);

    const int* src_g = eig;
    const int* dst_g = eig + Eg;
    const int* src_l = eil;
    const int* dst_l = eil + Elg;

    int mtE = (Eg + 127) / 128;   // 1563
    int mtN = (N + 127) / 128;    // 157

    // 1: weight prep; 2: encoder; 3: msg GEMM
    tsplit_all_kernel<<<(1179648 + 255) / 256, 256>>>(W_msg, W1, W2, p_wthi, p_wtlo);
    enc_kernel<<<N, 256>>>(x_g, W_enc, b_enc, p_node);
    {
        dim3 grid(4, mtN);
        mma_gemm_kernel<<<grid, 256, GEMM_SMEM>>>(
            p_node, p_wthi + OFF_WMSG, p_wtlo + OFF_WMSG,
            nullptr, nullptr, p_AB, nullptr, nullptr, N, 512, 256, 0);
    }
    basis4_both_kernel<<<(Eg + Elg + 255) / 256, 256>>>(
        edb, Wg_nb, bg_nb, p_nbg, Eg,
        ea_lg, Wg_eb, bg_eb, p_ebg, Elg);
    msg_edge_kernel<<<(Eg + MEPB - 1) / MEPB, 256>>>(
        p_AB, ea_g, x_lg, W_msg + 512 * H, W_msg + 528 * H, b_msg,
        src_g, dst_g, p_h, Eg);
    build_csr(dst_l, Eg, Elg, p_deg, p_blk, p_rp_lg, p_cursor, p_ei_lg);
    build_csr(dst_g, N, Eg, p_deg, p_blk, p_rp_g, p_cursor, p_ei_g);

    cudaMemsetAsync(p_bnacc, 0, 2 * H * sizeof(float));

    // --- 4 GENConv layers ---
    for (int l = 0; l < L; l++) {
        int use_bn = (l > 0) ? 1 : 0;
        if (use_bn) {
            bn_coef_kernel<<<1, 256>>>(p_bnacc, bn_gamma + (l - 1) * H, bn_beta + (l - 1) * H,
                                       p_bnsc, p_bnsh, Eg);
        }
        gen_aggr_kernel<<<(Eg + RPB - 1) / RPB, 256>>>(
            p_h, p_nbg, p_ebg,
            Wl_nb + l * 4 * H, bl_nb + l * H,
            Wl_eb + l * 4 * H, bl_eb + l * H,
            p_bnsc, p_bnsh, src_l, p_rp_lg, p_ei_lg,
            p_act, Eg, use_bn);

        // GEMM1: hid = relu(act @ W1 + b1), fp16 out
        {
            dim3 grid(4, mtE);
            mma_gemm_kernel<<<grid, 256, GEMM_SMEM>>>(
                p_act, p_wthi + OFF_W1T + l * 131072, p_wtlo + OFF_W1T + l * 131072,
                b1 + l * 512, nullptr, nullptr, p_hid, nullptr,
                Eg, 512, 256, 1 | 2 | 8);
        }
        // GEMM2: h = hid @ W2 + b2 (+ residual for l>0), fp32 out + fused BN stats
        {
            dim3 grid(2, mtE);
            mma_gemm_kernel<<<grid, 256, GEMM_SMEM>>>(
                p_hid, p_wthi + OFF_W2T + l * 131072, p_wtlo + OFF_W2T + l * 131072,
                b2 + l * 256, (l > 0) ? p_h : nullptr, p_h, nullptr, p_bnacc,
                Eg, 256, 512, ((l > 0) ? (1 | 4) : 1) | 32);
        }
    }

    // --- final BN coefs + fused node gather/pool ---
    bn_coef_kernel<<<1, 256>>>(p_bnacc, bn_gamma + 3 * H, bn_beta + 3 * H, p_bnsc, p_bnsh, Eg);

    cudaMemsetAsync(p_gsum, 0, NGRAPH * H * sizeof(float));
    cudaMemsetAsync(p_cnt,  0, NGRAPH * sizeof(float));
    node_pool_kernel<<<N, 256>>>(p_h, p_bnsc, p_bnsh, p_rp_g, p_ei_g, batch, p_gsum, p_cnt);
    predict_kernel<<<NGRAPH, 256>>>(p_gsum, p_cnt, W_pred, b_pred, (float*)d_out);
}